// round 2
// baseline (speedup 1.0000x reference)
#include <cuda_runtime.h>
#include <cstdint>
#include <cstddef>

// ---------------------------------------------------------------------------
// GCN: 3x GCNConv(128->128) + lin(128->128,relu) + lin(128->40) + log_softmax
// N=100000 nodes, F=128 features, E=1.6M edges.
// ---------------------------------------------------------------------------

#define NMAX 100000
#define F    128
#define NCLS 40

// Scratch (allocation-free: __device__ globals)
__device__ float g_H[(size_t)NMAX * F];     // h = A @ W          (51.2 MB)
__device__ float g_AGG[(size_t)NMAX * F];   // aggregate buffer   (51.2 MB)
__device__ float g_deg[NMAX];
__device__ float g_dinv[NMAX];
__device__ int   g_is64;

// ---------------------------------------------------------------------------
// edge_index dtype detection: reference declares int64 but JAX without x64
// silently produces int32. For int64 indices < 2^31, every odd 32-bit word
// is zero; for random int32 indices, essentially never. Sample 2048 words.
// ---------------------------------------------------------------------------
__global__ void detect_dtype_kernel(const unsigned int* __restrict__ w) {
    __shared__ int found;
    if (threadIdx.x == 0) found = 0;
    __syncthreads();
    for (int i = threadIdx.x; i < 2048; i += blockDim.x) {
        if (w[2 * i + 1] != 0u) atomicOr(&found, 1);
    }
    __syncthreads();
    if (threadIdx.x == 0) g_is64 = found ? 0 : 1;
}

__device__ __forceinline__ void load_edge(const void* ei, long long e, long long E,
                                          int& s, int& d) {
    if (g_is64) {
        const long long* p = (const long long*)ei;
        s = (int)p[e];
        d = (int)p[E + e];
    } else {
        const int* p = (const int*)ei;
        s = p[e];
        d = p[E + e];
    }
}

// ---------------------------------------------------------------------------
// Degree / normalization
// ---------------------------------------------------------------------------
__global__ void deg_init_kernel(int M) {
    int i = blockIdx.x * blockDim.x + threadIdx.x;
    if (i < M) g_deg[i] = 1.0f;  // self-loop
}

__global__ void deg_accum_kernel(const void* __restrict__ ei, int E) {
    int e = blockIdx.x * blockDim.x + threadIdx.x;
    if (e >= E) return;
    int s, d;
    load_edge(ei, e, E, s, d);
    atomicAdd(&g_deg[d], 1.0f);
}

__global__ void dinv_kernel(int M) {
    int i = blockIdx.x * blockDim.x + threadIdx.x;
    if (i < M) g_dinv[i] = rsqrtf(g_deg[i]);
}

// ---------------------------------------------------------------------------
// Tiled fp32 GEMM: C[M,128] = op(A)[M,128] @ W[128,128]
//  flags bit0: relu on A load (input from previous layer's AGG)
//  flags bit1: GCN epilogue:  g_H = h ; g_AGG = h * dinv[r]^2 + bias[c]
//  flags bit2: linear epilogue: g_H = relu(h + bias[c])
//  A == nullptr means "read from g_AGG".
// ---------------------------------------------------------------------------
#define BM 128
#define BN 128
#define BK 16
#define TM 8
#define TN 8

__global__ void __launch_bounds__(256, 1) gemm_kernel(
    const float* __restrict__ A, const float* __restrict__ W,
    const float* __restrict__ bias, int M, int flags)
{
    __shared__ float As[BK][BM + 4];  // transposed A tile
    __shared__ float Bs[BK][BN];

    const float* Ap = A ? A : g_AGG;
    const bool relu_in = flags & 1;

    const int tid = threadIdx.x;
    const int tx = tid & 15;   // 0..15 -> col group
    const int ty = tid >> 4;   // 0..15 -> row group
    const int row0 = blockIdx.x * BM;

    float acc[TM][TN];
#pragma unroll
    for (int i = 0; i < TM; i++)
#pragma unroll
        for (int j = 0; j < TN; j++) acc[i][j] = 0.0f;

    for (int k0 = 0; k0 < F; k0 += BK) {
        // Load A tile (BM x BK): 512 float4, 2 per thread; store transposed.
#pragma unroll
        for (int i = 0; i < 2; i++) {
            int lin = tid + i * 256;
            int r  = lin >> 2;   // 0..127
            int kg = lin & 3;    // 0..3
            float4 v = make_float4(0.f, 0.f, 0.f, 0.f);
            int grow = row0 + r;
            if (grow < M)
                v = *(const float4*)(Ap + (size_t)grow * F + k0 + kg * 4);
            if (relu_in) {
                v.x = fmaxf(v.x, 0.f); v.y = fmaxf(v.y, 0.f);
                v.z = fmaxf(v.z, 0.f); v.w = fmaxf(v.w, 0.f);
            }
            As[kg * 4 + 0][r] = v.x;
            As[kg * 4 + 1][r] = v.y;
            As[kg * 4 + 2][r] = v.z;
            As[kg * 4 + 3][r] = v.w;
        }
        // Load B tile (BK x BN): 512 float4, 2 per thread.
#pragma unroll
        for (int i = 0; i < 2; i++) {
            int lin = tid + i * 256;
            int r  = lin >> 5;   // 0..15
            int cg = lin & 31;   // 0..31
            float4 v = *(const float4*)(W + (size_t)(k0 + r) * F + cg * 4);
            *(float4*)&Bs[r][cg * 4] = v;
        }
        __syncthreads();

#pragma unroll
        for (int k = 0; k < BK; k++) {
            float a[TM], b[TN];
#pragma unroll
            for (int i = 0; i < TM; i++) a[i] = As[k][ty * TM + i];
#pragma unroll
            for (int j = 0; j < TN; j++) b[j] = Bs[k][tx * TN + j];
#pragma unroll
            for (int i = 0; i < TM; i++)
#pragma unroll
                for (int j = 0; j < TN; j++)
                    acc[i][j] = fmaf(a[i], b[j], acc[i][j]);
        }
        __syncthreads();
    }

    // Epilogue
#pragma unroll
    for (int i = 0; i < TM; i++) {
        int r = row0 + ty * TM + i;
        if (r >= M) continue;
        float sn = 0.0f;
        if (flags & 2) {
            float di = g_dinv[r];
            sn = di * di;
        }
#pragma unroll
        for (int j = 0; j < TN; j++) {
            int c = tx * TN + j;
            float h = acc[i][j];
            if (flags & 2) {
                g_H[(size_t)r * F + c]   = h;
                g_AGG[(size_t)r * F + c] = fmaf(h, sn, bias[c]);
            } else {
                g_H[(size_t)r * F + c] = fmaxf(h + bias[c], 0.0f);
            }
        }
    }
}

// ---------------------------------------------------------------------------
// Scatter: one warp per edge. g_AGG[dst] += g_H[src] * dinv[src]*dinv[dst]
// Vector fp32 reductions (sm_90+): red.global.add.v4.f32
// ---------------------------------------------------------------------------
__global__ void scatter_kernel(const void* __restrict__ ei, int E) {
    long long gw = ((long long)blockIdx.x * blockDim.x + threadIdx.x) >> 5;
    int lane = threadIdx.x & 31;
    if (gw >= E) return;
    int s, d;
    load_edge(ei, gw, E, s, d);
    float nrm = g_dinv[s] * g_dinv[d];
    float4 v = ((const float4*)(g_H + (size_t)s * F))[lane];
    float* dst = g_AGG + (size_t)d * F + lane * 4;
    asm volatile("red.global.add.v4.f32 [%0], {%1, %2, %3, %4};"
                 :: "l"(dst), "f"(v.x * nrm), "f"(v.y * nrm),
                    "f"(v.z * nrm), "f"(v.w * nrm)
                 : "memory");
}

// ---------------------------------------------------------------------------
// lin2 (128 -> 40) + log_softmax. One block (128 threads) per node.
// ---------------------------------------------------------------------------
__global__ void lin2_lsm_kernel(const float* __restrict__ W2,
                                const float* __restrict__ b2,
                                float* __restrict__ out, int M)
{
    __shared__ float row[F];
    __shared__ float logits[NCLS];
    __shared__ float lse;
    int n = blockIdx.x;
    int t = threadIdx.x;
    row[t] = g_H[(size_t)n * F + t];
    __syncthreads();
    if (t < NCLS) {
        float acc = b2[t];
#pragma unroll
        for (int k = 0; k < F; k++)
            acc = fmaf(row[k], W2[k * NCLS + t], acc);
        logits[t] = acc;
    }
    __syncthreads();
    if (t == 0) {
        float m = -1e30f;
        for (int c = 0; c < NCLS; c++) m = fmaxf(m, logits[c]);
        float s = 0.0f;
        for (int c = 0; c < NCLS; c++) s += expf(logits[c] - m);
        lse = m + logf(s);
    }
    __syncthreads();
    if (t < NCLS) out[(size_t)n * NCLS + t] = logits[t] - lse;
}

// ---------------------------------------------------------------------------
// Launch
// ---------------------------------------------------------------------------
extern "C" void kernel_launch(void* const* d_in, const int* in_sizes, int n_in,
                              void* d_out, int out_size) {
    const float* x      = (const float*)d_in[0];
    const void*  ei     = d_in[1];
    const float* W1     = (const float*)d_in[2];
    const float* b1     = (const float*)d_in[3];
    const float* W2     = (const float*)d_in[4];
    const float* b2     = (const float*)d_in[5];
    const float* W3     = (const float*)d_in[6];
    const float* b3     = (const float*)d_in[7];
    const float* lin1_w = (const float*)d_in[8];
    const float* lin1_b = (const float*)d_in[9];
    const float* lin2_w = (const float*)d_in[10];
    const float* lin2_b = (const float*)d_in[11];
    float* out = (float*)d_out;

    int M = in_sizes[0] / F;
    int E = in_sizes[1] / 2;

    // Normalization setup
    detect_dtype_kernel<<<1, 256>>>((const unsigned int*)ei);
    deg_init_kernel<<<(M + 255) / 256, 256>>>(M);
    deg_accum_kernel<<<(E + 255) / 256, 256>>>(ei, E);
    dinv_kernel<<<(M + 255) / 256, 256>>>(M);

    int gblocks = (M + BM - 1) / BM;
    long long scatter_threads = (long long)E * 32;
    int sblocks = (int)((scatter_threads + 255) / 256);

    // GCN layer 1: input x (no relu)
    gemm_kernel<<<gblocks, 256>>>(x, W1, b1, M, /*flags=*/2);
    scatter_kernel<<<sblocks, 256>>>(ei, E);
    // GCN layer 2: input relu(g_AGG)
    gemm_kernel<<<gblocks, 256>>>(nullptr, W2, b2, M, /*flags=*/3);
    scatter_kernel<<<sblocks, 256>>>(ei, E);
    // GCN layer 3
    gemm_kernel<<<gblocks, 256>>>(nullptr, W3, b3, M, /*flags=*/3);
    scatter_kernel<<<sblocks, 256>>>(ei, E);
    // lin1: g_H = relu(relu(g_AGG) @ lin1_w + lin1_b)
    gemm_kernel<<<gblocks, 256>>>(nullptr, lin1_w, lin1_b, M, /*flags=*/5);
    // lin2 + log_softmax
    lin2_lsm_kernel<<<M, 128>>>(lin2_w, lin2_b, out, M);
}

// round 3
// speedup vs baseline: 2.9352x; 2.9352x over previous
#include <cuda_runtime.h>
#include <cstdint>
#include <cstddef>

// ---------------------------------------------------------------------------
// GCN: 3x GCNConv(128->128) + lin(128->128,relu) + lin(128->40) + log_softmax
// tf32 tensor-core GEMMs + CSR-based atomic-free aggregation.
// ---------------------------------------------------------------------------

#define NMAX 100000
#define F    128
#define NCLS 40
#define EMAX 1600000

__device__ float g_H[(size_t)NMAX * F];     // h * dinv[row]  (51.2 MB)
__device__ float g_AGG[(size_t)NMAX * F];   // aggregate      (51.2 MB)
__device__ float g_dinv[NMAX];
__device__ int   g_cnt[NMAX];
__device__ int   g_off[NMAX + 1];
__device__ int   g_cur[NMAX];
__device__ int   g_blksum[128];
__device__ int   g_blkoff[128];
__device__ int   g_csr[EMAX];
__device__ float g_W2p[F * F];
__device__ float g_b2p[F];
__device__ int   g_is64;

// ---------------------------------------------------------------------------
// edge_index dtype detection (int64 declared, JAX may emit int32)
// ---------------------------------------------------------------------------
__global__ void detect_dtype_kernel(const unsigned int* __restrict__ w) {
    __shared__ int found;
    if (threadIdx.x == 0) found = 0;
    __syncthreads();
    for (int i = threadIdx.x; i < 2048; i += blockDim.x)
        if (w[2 * i + 1] != 0u) atomicOr(&found, 1);
    __syncthreads();
    if (threadIdx.x == 0) g_is64 = found ? 0 : 1;
}

__device__ __forceinline__ void load_edge(const void* ei, long long e, long long E,
                                          int& s, int& d) {
    if (g_is64) {
        const long long* p = (const long long*)ei;
        s = (int)p[e];
        d = (int)p[E + e];
    } else {
        const int* p = (const int*)ei;
        s = p[e];
        d = p[E + e];
    }
}

// ---------------------------------------------------------------------------
// CSR build: histogram -> prefix scan -> fill
// ---------------------------------------------------------------------------
__global__ void cnt_zero_kernel(int M) {
    int i = blockIdx.x * blockDim.x + threadIdx.x;
    if (i < M) g_cnt[i] = 0;
}

__global__ void cnt_hist_kernel(const void* __restrict__ ei, int E) {
    int e = blockIdx.x * blockDim.x + threadIdx.x;
    if (e >= E) return;
    int s, d;
    load_edge(ei, e, E, s, d);
    atomicAdd(&g_cnt[d], 1);
}

__global__ void chunksum_kernel(int M) {
    __shared__ int sh[256];
    int b = blockIdx.x, t = threadIdx.x;
    int base = b * 1024 + t * 4, s = 0;
#pragma unroll
    for (int j = 0; j < 4; j++) {
        int i = base + j;
        if (i < M) s += g_cnt[i];
    }
    sh[t] = s;
    __syncthreads();
    for (int o = 128; o; o >>= 1) {
        if (t < o) sh[t] += sh[t + o];
        __syncthreads();
    }
    if (t == 0) g_blksum[b] = sh[0];
}

__global__ void scanblk_kernel(int NB, int M, int E) {
    __shared__ int sh[128];
    int t = threadIdx.x;
    int v = (t < NB) ? g_blksum[t] : 0;
    sh[t] = v;
    __syncthreads();
    for (int o = 1; o < 128; o <<= 1) {
        int u = (t >= o) ? sh[t - o] : 0;
        __syncthreads();
        sh[t] += u;
        __syncthreads();
    }
    g_blkoff[t] = sh[t] - v;
    if (t == 0) g_off[M] = E;
}

__global__ void chunkscan_kernel(int M) {
    __shared__ int sh[256];
    int b = blockIdx.x, t = threadIdx.x;
    int base = b * 1024 + t * 4;
    int v[4], s = 0;
#pragma unroll
    for (int j = 0; j < 4; j++) {
        int i = base + j;
        v[j] = (i < M) ? g_cnt[i] : 0;
        s += v[j];
    }
    sh[t] = s;
    __syncthreads();
    for (int o = 1; o < 256; o <<= 1) {
        int u = (t >= o) ? sh[t - o] : 0;
        __syncthreads();
        sh[t] += u;
        __syncthreads();
    }
    int run = g_blkoff[b] + sh[t] - s;
#pragma unroll
    for (int j = 0; j < 4; j++) {
        int i = base + j;
        if (i < M) {
            g_off[i] = run;
            g_cur[i] = run;
            run += v[j];
        }
    }
}

__global__ void csr_fill_kernel(const void* __restrict__ ei, int E) {
    int e = blockIdx.x * blockDim.x + threadIdx.x;
    if (e >= E) return;
    int s, d;
    load_edge(ei, e, E, s, d);
    int p = atomicAdd(&g_cur[d], 1);
    g_csr[p] = s;
}

__global__ void dinv_kernel(int M) {
    int i = blockIdx.x * blockDim.x + threadIdx.x;
    if (i < M) g_dinv[i] = rsqrtf((float)g_cnt[i] + 1.0f);
}

// Pad lin2 weights [128,40] -> [128,128] with zeros, bias likewise.
__global__ void pad_w2_kernel(const float* __restrict__ w, const float* __restrict__ b) {
    int idx = blockIdx.x * blockDim.x + threadIdx.x;
    if (idx < F * F) {
        int r = idx >> 7, c = idx & 127;
        g_W2p[idx] = (c < NCLS) ? w[r * NCLS + c] : 0.0f;
    }
    if (idx < F) g_b2p[idx] = (idx < NCLS) ? b[idx] : 0.0f;
}

// ---------------------------------------------------------------------------
// tf32 tensor-core GEMM: C[M,128] = op(A)[M,128] @ W[128,128]
//  flags bit0: relu on A load
//  flags bit1: GCN epilogue:  g_H = h*dinv[r]; g_AGG = h*dinv[r]^2 + b
//  flags bit2: linear epilogue: g_H = relu(h + b)
//  else:       plain epilogue: g_AGG = h + b
//  asel: 0=A param, 1=g_AGG, 2=g_H.   W==nullptr -> g_W2p, bias==nullptr -> g_b2p
// ---------------------------------------------------------------------------
#define BM 128
#define BN 128
#define BK 32

__device__ __forceinline__ uint32_t f2tf32(float x) {
    uint32_t u;
    asm("cvt.rna.tf32.f32 %0, %1;" : "=r"(u) : "f"(x));
    return u;
}

__device__ __forceinline__ void mma_tf32(float* d, const uint32_t* a, const uint32_t* b) {
    asm volatile(
        "mma.sync.aligned.m16n8k8.row.col.f32.tf32.tf32.f32 "
        "{%0,%1,%2,%3}, {%4,%5,%6,%7}, {%8,%9}, {%0,%1,%2,%3};"
        : "+f"(d[0]), "+f"(d[1]), "+f"(d[2]), "+f"(d[3])
        : "r"(a[0]), "r"(a[1]), "r"(a[2]), "r"(a[3]), "r"(b[0]), "r"(b[1]));
}

__global__ void __launch_bounds__(256) gemm_tc_kernel(
    const float* __restrict__ A, const float* __restrict__ Wt,
    const float* __restrict__ bias, int M, int flags, int asel)
{
    __shared__ uint32_t As[BK][BM + 4];
    __shared__ uint32_t Ws[BK][BN + 4];

    const float* Ap = (asel == 0) ? A : (asel == 1 ? g_AGG : g_H);
    const float* Wp = Wt ? Wt : g_W2p;
    const float* bp = bias ? bias : g_b2p;
    const bool relu_in = flags & 1;

    const int tid = threadIdx.x;
    const int lane = tid & 31;
    const int wid = tid >> 5;
    const int wm = wid & 1;    // 2 warp-rows of 64
    const int wn = wid >> 1;   // 4 warp-cols of 32
    const int tg = lane >> 2;  // 0..7
    const int tm = lane & 3;   // 0..3
    const int row0 = blockIdx.x * BM;

    float acc[4][4][4];
#pragma unroll
    for (int mt = 0; mt < 4; mt++)
#pragma unroll
        for (int nt = 0; nt < 4; nt++)
#pragma unroll
            for (int j = 0; j < 4; j++) acc[mt][nt][j] = 0.0f;

    for (int k0 = 0; k0 < F; k0 += BK) {
        // A tile 128x32 (4 float4 per thread)
#pragma unroll
        for (int p = 0; p < 4; p++) {
            int lin = p * 256 + tid;
            int r = lin >> 3;
            int c4 = (lin & 7) * 4;
            float4 v = make_float4(0.f, 0.f, 0.f, 0.f);
            int gr = row0 + r;
            if (gr < M) v = *(const float4*)(Ap + (size_t)gr * F + k0 + c4);
            if (relu_in) {
                v.x = fmaxf(v.x, 0.f); v.y = fmaxf(v.y, 0.f);
                v.z = fmaxf(v.z, 0.f); v.w = fmaxf(v.w, 0.f);
            }
            As[c4 + 0][r] = f2tf32(v.x);
            As[c4 + 1][r] = f2tf32(v.y);
            As[c4 + 2][r] = f2tf32(v.z);
            As[c4 + 3][r] = f2tf32(v.w);
        }
        // W tile 32x128
#pragma unroll
        for (int p = 0; p < 4; p++) {
            int lin = p * 256 + tid;
            int r = lin >> 5;
            int c4 = (lin & 31) * 4;
            float4 v = *(const float4*)(Wp + (size_t)(k0 + r) * F + c4);
            Ws[r][c4 + 0] = f2tf32(v.x);
            Ws[r][c4 + 1] = f2tf32(v.y);
            Ws[r][c4 + 2] = f2tf32(v.z);
            Ws[r][c4 + 3] = f2tf32(v.w);
        }
        __syncthreads();

#pragma unroll
        for (int kk = 0; kk < 4; kk++) {
            int kb = kk * 8;
            uint32_t af[4][4], bf[4][2];
#pragma unroll
            for (int mt = 0; mt < 4; mt++) {
                int rb = wm * 64 + mt * 16 + tg;
                af[mt][0] = As[kb + tm][rb];
                af[mt][1] = As[kb + tm][rb + 8];
                af[mt][2] = As[kb + tm + 4][rb];
                af[mt][3] = As[kb + tm + 4][rb + 8];
            }
#pragma unroll
            for (int nt = 0; nt < 4; nt++) {
                int nb = wn * 32 + nt * 8 + tg;
                bf[nt][0] = Ws[kb + tm][nb];
                bf[nt][1] = Ws[kb + tm + 4][nb];
            }
#pragma unroll
            for (int mt = 0; mt < 4; mt++)
#pragma unroll
                for (int nt = 0; nt < 4; nt++)
                    mma_tf32(acc[mt][nt], af[mt], bf[nt]);
        }
        __syncthreads();
    }

    // Epilogue
#pragma unroll
    for (int mt = 0; mt < 4; mt++) {
        int r0 = row0 + wm * 64 + mt * 16 + tg;
        int r1 = r0 + 8;
        float dv0 = 0.f, dv1 = 0.f;
        if (flags & 2) {
            if (r0 < M) dv0 = g_dinv[r0];
            if (r1 < M) dv1 = g_dinv[r1];
        }
#pragma unroll
        for (int nt = 0; nt < 4; nt++) {
            int c = wn * 32 + nt * 8 + tm * 2;
            float b0 = bp[c], b1 = bp[c + 1];
            float h00 = acc[mt][nt][0], h01 = acc[mt][nt][1];
            float h10 = acc[mt][nt][2], h11 = acc[mt][nt][3];
            if (flags & 2) {
                if (r0 < M) {
                    float s0 = h00 * dv0, s1 = h01 * dv0;
                    *(float2*)&g_H[(size_t)r0 * F + c] = make_float2(s0, s1);
                    *(float2*)&g_AGG[(size_t)r0 * F + c] =
                        make_float2(fmaf(s0, dv0, b0), fmaf(s1, dv0, b1));
                }
                if (r1 < M) {
                    float s0 = h10 * dv1, s1 = h11 * dv1;
                    *(float2*)&g_H[(size_t)r1 * F + c] = make_float2(s0, s1);
                    *(float2*)&g_AGG[(size_t)r1 * F + c] =
                        make_float2(fmaf(s0, dv1, b0), fmaf(s1, dv1, b1));
                }
            } else if (flags & 4) {
                if (r0 < M)
                    *(float2*)&g_H[(size_t)r0 * F + c] =
                        make_float2(fmaxf(h00 + b0, 0.f), fmaxf(h01 + b1, 0.f));
                if (r1 < M)
                    *(float2*)&g_H[(size_t)r1 * F + c] =
                        make_float2(fmaxf(h10 + b0, 0.f), fmaxf(h11 + b1, 0.f));
            } else {
                if (r0 < M)
                    *(float2*)&g_AGG[(size_t)r0 * F + c] = make_float2(h00 + b0, h01 + b1);
                if (r1 < M)
                    *(float2*)&g_AGG[(size_t)r1 * F + c] = make_float2(h10 + b0, h11 + b1);
            }
        }
    }
}

// ---------------------------------------------------------------------------
// CSR aggregation: one warp per node. g_AGG[n] += dinv[n] * sum(g_H[src])
// (g_H is pre-scaled by dinv[src]; g_AGG pre-initialized with self + bias)
// ---------------------------------------------------------------------------
__global__ void agg_kernel(int M) {
    long long gw = ((long long)blockIdx.x * blockDim.x + threadIdx.x) >> 5;
    if (gw >= M) return;
    int n = (int)gw;
    int lane = threadIdx.x & 31;
    int e = g_off[n], e1 = g_off[n + 1];
    const float4* H4 = (const float4*)g_H;
    float4 acc = make_float4(0.f, 0.f, 0.f, 0.f);
    for (; e + 1 < e1; e += 2) {
        int s0 = __ldg(&g_csr[e]);
        int s1 = __ldg(&g_csr[e + 1]);
        float4 v0 = H4[(size_t)s0 * 32 + lane];
        float4 v1 = H4[(size_t)s1 * 32 + lane];
        acc.x += v0.x + v1.x;
        acc.y += v0.y + v1.y;
        acc.z += v0.z + v1.z;
        acc.w += v0.w + v1.w;
    }
    if (e < e1) {
        int s0 = __ldg(&g_csr[e]);
        float4 v0 = H4[(size_t)s0 * 32 + lane];
        acc.x += v0.x; acc.y += v0.y; acc.z += v0.z; acc.w += v0.w;
    }
    float dn = g_dinv[n];
    float4 r = ((const float4*)g_AGG)[(size_t)n * 32 + lane];
    r.x = fmaf(acc.x, dn, r.x);
    r.y = fmaf(acc.y, dn, r.y);
    r.z = fmaf(acc.z, dn, r.z);
    r.w = fmaf(acc.w, dn, r.w);
    ((float4*)g_AGG)[(size_t)n * 32 + lane] = r;
}

// ---------------------------------------------------------------------------
// log_softmax over 40 logits (in g_AGG cols 0..39). One warp per node.
// ---------------------------------------------------------------------------
__global__ void lsm_kernel(float* __restrict__ out, int M) {
    long long gw = ((long long)blockIdx.x * blockDim.x + threadIdx.x) >> 5;
    if (gw >= M) return;
    int n = (int)gw;
    int lane = threadIdx.x & 31;
    float v0 = g_AGG[(size_t)n * F + lane];
    float v1 = (lane < 8) ? g_AGG[(size_t)n * F + 32 + lane] : -1e30f;
    float m = fmaxf(v0, v1);
#pragma unroll
    for (int o = 16; o; o >>= 1) m = fmaxf(m, __shfl_xor_sync(0xffffffffu, m, o));
    float s = expf(v0 - m) + ((lane < 8) ? expf(v1 - m) : 0.f);
#pragma unroll
    for (int o = 16; o; o >>= 1) s += __shfl_xor_sync(0xffffffffu, s, o);
    float lse = m + logf(s);
    out[(size_t)n * NCLS + lane] = v0 - lse;
    if (lane < 8) out[(size_t)n * NCLS + 32 + lane] = v1 - lse;
}

// ---------------------------------------------------------------------------
// Launch
// ---------------------------------------------------------------------------
extern "C" void kernel_launch(void* const* d_in, const int* in_sizes, int n_in,
                              void* d_out, int out_size) {
    const float* x      = (const float*)d_in[0];
    const void*  ei     = d_in[1];
    const float* W1     = (const float*)d_in[2];
    const float* b1     = (const float*)d_in[3];
    const float* W2     = (const float*)d_in[4];
    const float* b2     = (const float*)d_in[5];
    const float* W3     = (const float*)d_in[6];
    const float* b3     = (const float*)d_in[7];
    const float* lin1_w = (const float*)d_in[8];
    const float* lin1_b = (const float*)d_in[9];
    const float* lin2_w = (const float*)d_in[10];
    const float* lin2_b = (const float*)d_in[11];
    float* out = (float*)d_out;

    int M = in_sizes[0] / F;
    int E = in_sizes[1] / 2;
    int NB = (M + 1023) / 1024;

    detect_dtype_kernel<<<1, 256>>>((const unsigned int*)ei);
    cnt_zero_kernel<<<(M + 255) / 256, 256>>>(M);
    cnt_hist_kernel<<<(E + 255) / 256, 256>>>(ei, E);
    chunksum_kernel<<<NB, 256>>>(M);
    scanblk_kernel<<<1, 128>>>(NB, M, E);
    chunkscan_kernel<<<NB, 256>>>(M);
    csr_fill_kernel<<<(E + 255) / 256, 256>>>(ei, E);
    dinv_kernel<<<(M + 255) / 256, 256>>>(M);
    pad_w2_kernel<<<(F * F + 255) / 256, 256>>>(lin2_w, lin2_b);

    int gb = (M + BM - 1) / BM;
    int wb = (int)(((long long)M * 32 + 255) / 256);

    // layer 1
    gemm_tc_kernel<<<gb, 256>>>(x, W1, b1, M, /*flags=*/2, /*asel=*/0);
    agg_kernel<<<wb, 256>>>(M);
    // layer 2
    gemm_tc_kernel<<<gb, 256>>>(nullptr, W2, b2, M, /*flags=*/3, /*asel=*/1);
    agg_kernel<<<wb, 256>>>(M);
    // layer 3
    gemm_tc_kernel<<<gb, 256>>>(nullptr, W3, b3, M, /*flags=*/3, /*asel=*/1);
    agg_kernel<<<wb, 256>>>(M);
    // lin1: g_H = relu(relu(AGG) @ lin1_w + b)
    gemm_tc_kernel<<<gb, 256>>>(nullptr, lin1_w, lin1_b, M, /*flags=*/5, /*asel=*/1);
    // lin2 (padded): g_AGG = g_H @ W2p + b2p
    gemm_tc_kernel<<<gb, 256>>>(nullptr, nullptr, nullptr, M, /*flags=*/0, /*asel=*/2);
    // log_softmax
    lsm_kernel<<<wb, 256>>>(out, M);
}

// round 4
// speedup vs baseline: 3.1391x; 1.0695x over previous
#include <cuda_runtime.h>
#include <cuda_fp16.h>
#include <cstdint>
#include <cstddef>

// ---------------------------------------------------------------------------
// GCN: 3x GCNConv(128->128) + lin(128->128,relu) + lin(128->40) + log_softmax
// tf32 tensor-core GEMMs, fp16 activation storage, CSR atomic-free gather.
// ---------------------------------------------------------------------------

#define NMAX 100000
#define F    128
#define NCLS 40
#define EMAX 1600000

__device__ __half g_H[(size_t)NMAX * F];    // h * dinv[row]   (25.6 MB)
__device__ __half g_AGG[(size_t)NMAX * F];  // aggregate       (25.6 MB)
__device__ float  g_LOG[(size_t)NMAX * F];  // fp32 logits (only cols < 40 used)
__device__ float  g_dinv[NMAX];
__device__ int    g_cnt[NMAX];
__device__ int    g_off[NMAX + 1];
__device__ int    g_cur[NMAX];
__device__ int    g_blksum[128];
__device__ int    g_blkoff[128];
__device__ int    g_csr[EMAX];
__device__ float  g_W2p[F * F];
__device__ float  g_b2p[F];
__device__ int    g_is64;

// ---------------------------------------------------------------------------
// half4 <-> float4 helpers (4 halves packed as uint2)
// ---------------------------------------------------------------------------
__device__ __forceinline__ float4 h4tof4(uint2 u) {
    __half2 a = *(__half2*)&u.x, b = *(__half2*)&u.y;
    float2 fa = __half22float2(a), fb = __half22float2(b);
    return make_float4(fa.x, fa.y, fb.x, fb.y);
}
__device__ __forceinline__ uint2 f4toh4(float4 v) {
    __half2 a = __floats2half2_rn(v.x, v.y);
    __half2 b = __floats2half2_rn(v.z, v.w);
    uint2 u;
    u.x = *(unsigned int*)&a;
    u.y = *(unsigned int*)&b;
    return u;
}

// ---------------------------------------------------------------------------
// Fused setup: dtype detect (block 0) + cnt zero + lin2 weight padding
// ---------------------------------------------------------------------------
__global__ void setup0_kernel(const unsigned int* __restrict__ w,
                              const float* __restrict__ w2,
                              const float* __restrict__ b2, int M) {
    if (blockIdx.x == 0) {
        __shared__ int found;
        if (threadIdx.x == 0) found = 0;
        __syncthreads();
        for (int i = threadIdx.x; i < 2048; i += blockDim.x)
            if (w[2 * i + 1] != 0u) atomicOr(&found, 1);
        __syncthreads();
        if (threadIdx.x == 0) g_is64 = found ? 0 : 1;
    }
    int stride = gridDim.x * blockDim.x;
    for (int i = blockIdx.x * blockDim.x + threadIdx.x; i < M; i += stride)
        g_cnt[i] = 0;
    for (int idx = blockIdx.x * blockDim.x + threadIdx.x; idx < F * F; idx += stride) {
        int r = idx >> 7, c = idx & 127;
        g_W2p[idx] = (c < NCLS) ? w2[r * NCLS + c] : 0.0f;
        if (idx < F) g_b2p[idx] = (idx < NCLS) ? b2[idx] : 0.0f;
    }
}

__device__ __forceinline__ void load_edge(const void* ei, long long e, long long E,
                                          int& s, int& d) {
    if (g_is64) {
        const long long* p = (const long long*)ei;
        s = (int)p[e];
        d = (int)p[E + e];
    } else {
        const int* p = (const int*)ei;
        s = p[e];
        d = p[E + e];
    }
}

// ---------------------------------------------------------------------------
// CSR build
// ---------------------------------------------------------------------------
__global__ void cnt_hist_kernel(const void* __restrict__ ei, int E) {
    int e = blockIdx.x * blockDim.x + threadIdx.x;
    if (e >= E) return;
    int s, d;
    load_edge(ei, e, E, s, d);
    atomicAdd(&g_cnt[d], 1);
}

// chunk sums (1024 nodes/block) + dinv fused
__global__ void chunksum_kernel(int M) {
    __shared__ int sh[256];
    int b = blockIdx.x, t = threadIdx.x;
    int base = b * 1024 + t * 4, s = 0;
#pragma unroll
    for (int j = 0; j < 4; j++) {
        int i = base + j;
        if (i < M) {
            int c = g_cnt[i];
            s += c;
            g_dinv[i] = rsqrtf((float)c + 1.0f);
        }
    }
    sh[t] = s;
    __syncthreads();
    for (int o = 128; o; o >>= 1) {
        if (t < o) sh[t] += sh[t + o];
        __syncthreads();
    }
    if (t == 0) g_blksum[b] = sh[0];
}

__global__ void scanblk_kernel(int NB, int M, int E) {
    __shared__ int sh[128];
    int t = threadIdx.x;
    int v = (t < NB) ? g_blksum[t] : 0;
    sh[t] = v;
    __syncthreads();
    for (int o = 1; o < 128; o <<= 1) {
        int u = (t >= o) ? sh[t - o] : 0;
        __syncthreads();
        sh[t] += u;
        __syncthreads();
    }
    g_blkoff[t] = sh[t] - v;
    if (t == 0) g_off[M] = E;
}

__global__ void chunkscan_kernel(int M) {
    __shared__ int sh[256];
    int b = blockIdx.x, t = threadIdx.x;
    int base = b * 1024 + t * 4;
    int v[4], s = 0;
#pragma unroll
    for (int j = 0; j < 4; j++) {
        int i = base + j;
        v[j] = (i < M) ? g_cnt[i] : 0;
        s += v[j];
    }
    sh[t] = s;
    __syncthreads();
    for (int o = 1; o < 256; o <<= 1) {
        int u = (t >= o) ? sh[t - o] : 0;
        __syncthreads();
        sh[t] += u;
        __syncthreads();
    }
    int run = g_blkoff[b] + sh[t] - s;
#pragma unroll
    for (int j = 0; j < 4; j++) {
        int i = base + j;
        if (i < M) {
            g_off[i] = run;
            g_cur[i] = run;
            run += v[j];
        }
    }
}

__global__ void csr_fill_kernel(const void* __restrict__ ei, int E) {
    int e = blockIdx.x * blockDim.x + threadIdx.x;
    if (e >= E) return;
    int s, d;
    load_edge(ei, e, E, s, d);
    int p = atomicAdd(&g_cur[d], 1);
    g_csr[p] = s;
}

// ---------------------------------------------------------------------------
// tf32 tensor-core GEMM: C[M,128] = op(A)[M,128] @ W[128,128]
//  flags bit0: relu on A load
//  flags bit1: GCN out:   g_H (half) = h * dinv[r]
//  flags bit2: lin1 out:  g_H (half) = relu(h + b)
//  flags bit3: logit out: g_LOG (fp32) = h + b, cols < NCLS only
//  asel: 0 = A param (fp32), 1 = g_AGG (half), 2 = g_H (half)
// ---------------------------------------------------------------------------
#define BM 128
#define BN 128
#define BK 32

__device__ __forceinline__ uint32_t f2tf32(float x) {
    uint32_t u;
    asm("cvt.rna.tf32.f32 %0, %1;" : "=r"(u) : "f"(x));
    return u;
}

__device__ __forceinline__ void mma_tf32(float* d, const uint32_t* a, const uint32_t* b) {
    asm volatile(
        "mma.sync.aligned.m16n8k8.row.col.f32.tf32.tf32.f32 "
        "{%0,%1,%2,%3}, {%4,%5,%6,%7}, {%8,%9}, {%0,%1,%2,%3};"
        : "+f"(d[0]), "+f"(d[1]), "+f"(d[2]), "+f"(d[3])
        : "r"(a[0]), "r"(a[1]), "r"(a[2]), "r"(a[3]), "r"(b[0]), "r"(b[1]));
}

__global__ void __launch_bounds__(256) gemm_tc_kernel(
    const float* __restrict__ A, const float* __restrict__ Wt,
    const float* __restrict__ bias, int M, int flags, int asel)
{
    __shared__ uint32_t As[BK][BM + 4];
    __shared__ uint32_t Ws[BK][BN + 4];

    const __half* Ah = (asel == 1) ? g_AGG : g_H;
    const float* Wp = Wt ? Wt : g_W2p;
    const float* bp = bias ? bias : g_b2p;
    const bool relu_in = flags & 1;
    const bool a_half = (asel != 0);

    const int tid = threadIdx.x;
    const int lane = tid & 31;
    const int wid = tid >> 5;
    const int wm = wid & 1;
    const int wn = wid >> 1;
    const int tg = lane >> 2;
    const int tm = lane & 3;
    const int row0 = blockIdx.x * BM;

    float acc[4][4][4];
#pragma unroll
    for (int mt = 0; mt < 4; mt++)
#pragma unroll
        for (int nt = 0; nt < 4; nt++)
#pragma unroll
            for (int j = 0; j < 4; j++) acc[mt][nt][j] = 0.0f;

    for (int k0 = 0; k0 < F; k0 += BK) {
        // A tile 128x32
#pragma unroll
        for (int p = 0; p < 4; p++) {
            int lin = p * 256 + tid;
            int r = lin >> 3;
            int c4 = (lin & 7) * 4;
            float4 v = make_float4(0.f, 0.f, 0.f, 0.f);
            int gr = row0 + r;
            if (gr < M) {
                size_t off = (size_t)gr * F + k0 + c4;
                if (a_half) {
                    uint2 u = *(const uint2*)(Ah + off);
                    v = h4tof4(u);
                } else {
                    v = *(const float4*)(A + off);
                }
            }
            if (relu_in) {
                v.x = fmaxf(v.x, 0.f); v.y = fmaxf(v.y, 0.f);
                v.z = fmaxf(v.z, 0.f); v.w = fmaxf(v.w, 0.f);
            }
            As[c4 + 0][r] = f2tf32(v.x);
            As[c4 + 1][r] = f2tf32(v.y);
            As[c4 + 2][r] = f2tf32(v.z);
            As[c4 + 3][r] = f2tf32(v.w);
        }
        // W tile 32x128
#pragma unroll
        for (int p = 0; p < 4; p++) {
            int lin = p * 256 + tid;
            int r = lin >> 5;
            int c4 = (lin & 31) * 4;
            float4 v = *(const float4*)(Wp + (size_t)(k0 + r) * F + c4);
            Ws[r][c4 + 0] = f2tf32(v.x);
            Ws[r][c4 + 1] = f2tf32(v.y);
            Ws[r][c4 + 2] = f2tf32(v.z);
            Ws[r][c4 + 3] = f2tf32(v.w);
        }
        __syncthreads();

#pragma unroll
        for (int kk = 0; kk < 4; kk++) {
            int kb = kk * 8;
            uint32_t af[4][4], bf[4][2];
#pragma unroll
            for (int mt = 0; mt < 4; mt++) {
                int rb = wm * 64 + mt * 16 + tg;
                af[mt][0] = As[kb + tm][rb];
                af[mt][1] = As[kb + tm][rb + 8];
                af[mt][2] = As[kb + tm + 4][rb];
                af[mt][3] = As[kb + tm + 4][rb + 8];
            }
#pragma unroll
            for (int nt = 0; nt < 4; nt++) {
                int nb = wn * 32 + nt * 8 + tg;
                bf[nt][0] = Ws[kb + tm][nb];
                bf[nt][1] = Ws[kb + tm + 4][nb];
            }
#pragma unroll
            for (int mt = 0; mt < 4; mt++)
#pragma unroll
                for (int nt = 0; nt < 4; nt++)
                    mma_tf32(acc[mt][nt], af[mt], bf[nt]);
        }
        __syncthreads();
    }

    // Epilogue
#pragma unroll
    for (int mt = 0; mt < 4; mt++) {
        int r0 = row0 + wm * 64 + mt * 16 + tg;
        int r1 = r0 + 8;
        float dv0 = 0.f, dv1 = 0.f;
        if (flags & 2) {
            if (r0 < M) dv0 = g_dinv[r0];
            if (r1 < M) dv1 = g_dinv[r1];
        }
#pragma unroll
        for (int nt = 0; nt < 4; nt++) {
            int c = wn * 32 + nt * 8 + tm * 2;
            float b0 = bp[c], b1 = bp[c + 1];
            float h00 = acc[mt][nt][0], h01 = acc[mt][nt][1];
            float h10 = acc[mt][nt][2], h11 = acc[mt][nt][3];
            if (flags & 2) {
                if (r0 < M)
                    *(__half2*)&g_H[(size_t)r0 * F + c] =
                        __floats2half2_rn(h00 * dv0, h01 * dv0);
                if (r1 < M)
                    *(__half2*)&g_H[(size_t)r1 * F + c] =
                        __floats2half2_rn(h10 * dv1, h11 * dv1);
            } else if (flags & 4) {
                if (r0 < M)
                    *(__half2*)&g_H[(size_t)r0 * F + c] =
                        __floats2half2_rn(fmaxf(h00 + b0, 0.f), fmaxf(h01 + b1, 0.f));
                if (r1 < M)
                    *(__half2*)&g_H[(size_t)r1 * F + c] =
                        __floats2half2_rn(fmaxf(h10 + b0, 0.f), fmaxf(h11 + b1, 0.f));
            } else {  // logits, fp32, cols < NCLS
                if (c < NCLS) {
                    if (r0 < M)
                        *(float2*)&g_LOG[(size_t)r0 * F + c] = make_float2(h00 + b0, h01 + b1);
                    if (r1 < M)
                        *(float2*)&g_LOG[(size_t)r1 * F + c] = make_float2(h10 + b0, h11 + b1);
                }
            }
        }
    }
}

// ---------------------------------------------------------------------------
// CSR aggregation, one warp per node:
//   g_AGG[n] = dinv[n] * (sum_{s in N(n)} g_H[s] + g_H[n]) + bias
// (g_H pre-scaled by dinv[src]; self-loop folded in here.)
// ---------------------------------------------------------------------------
__global__ void agg_kernel(const float* __restrict__ bias, int M) {
    long long gw = ((long long)blockIdx.x * blockDim.x + threadIdx.x) >> 5;
    if (gw >= M) return;
    int n = (int)gw;
    int lane = threadIdx.x & 31;
    const uint2* H2 = (const uint2*)g_H;  // 4 halves per element, 32 per row
    int e = g_off[n], e1 = g_off[n + 1];

    float4 acc = h4tof4(H2[(size_t)n * 32 + lane]);  // self term
    for (; e + 3 < e1; e += 4) {
        int s0 = __ldg(&g_csr[e]);
        int s1 = __ldg(&g_csr[e + 1]);
        int s2 = __ldg(&g_csr[e + 2]);
        int s3 = __ldg(&g_csr[e + 3]);
        float4 v0 = h4tof4(H2[(size_t)s0 * 32 + lane]);
        float4 v1 = h4tof4(H2[(size_t)s1 * 32 + lane]);
        float4 v2 = h4tof4(H2[(size_t)s2 * 32 + lane]);
        float4 v3 = h4tof4(H2[(size_t)s3 * 32 + lane]);
        acc.x += (v0.x + v1.x) + (v2.x + v3.x);
        acc.y += (v0.y + v1.y) + (v2.y + v3.y);
        acc.z += (v0.z + v1.z) + (v2.z + v3.z);
        acc.w += (v0.w + v1.w) + (v2.w + v3.w);
    }
    for (; e < e1; e++) {
        int s0 = __ldg(&g_csr[e]);
        float4 v0 = h4tof4(H2[(size_t)s0 * 32 + lane]);
        acc.x += v0.x; acc.y += v0.y; acc.z += v0.z; acc.w += v0.w;
    }
    float dn = g_dinv[n];
    float4 b = ((const float4*)bias)[lane];
    float4 r;
    r.x = fmaf(acc.x, dn, b.x);
    r.y = fmaf(acc.y, dn, b.y);
    r.z = fmaf(acc.z, dn, b.z);
    r.w = fmaf(acc.w, dn, b.w);
    ((uint2*)g_AGG)[(size_t)n * 32 + lane] = f4toh4(r);
}

// ---------------------------------------------------------------------------
// log_softmax over 40 fp32 logits. One warp per node.
// ---------------------------------------------------------------------------
__global__ void lsm_kernel(float* __restrict__ out, int M) {
    long long gw = ((long long)blockIdx.x * blockDim.x + threadIdx.x) >> 5;
    if (gw >= M) return;
    int n = (int)gw;
    int lane = threadIdx.x & 31;
    float v0 = g_LOG[(size_t)n * F + lane];
    float v1 = (lane < 8) ? g_LOG[(size_t)n * F + 32 + lane] : -1e30f;
    float m = fmaxf(v0, v1);
#pragma unroll
    for (int o = 16; o; o >>= 1) m = fmaxf(m, __shfl_xor_sync(0xffffffffu, m, o));
    float s = expf(v0 - m) + ((lane < 8) ? expf(v1 - m) : 0.f);
#pragma unroll
    for (int o = 16; o; o >>= 1) s += __shfl_xor_sync(0xffffffffu, s, o);
    float lse = m + logf(s);
    out[(size_t)n * NCLS + lane] = v0 - lse;
    if (lane < 8) out[(size_t)n * NCLS + 32 + lane] = v1 - lse;
}

// ---------------------------------------------------------------------------
// Launch
// ---------------------------------------------------------------------------
extern "C" void kernel_launch(void* const* d_in, const int* in_sizes, int n_in,
                              void* d_out, int out_size) {
    const float* x      = (const float*)d_in[0];
    const void*  ei     = d_in[1];
    const float* W1     = (const float*)d_in[2];
    const float* b1     = (const float*)d_in[3];
    const float* W2     = (const float*)d_in[4];
    const float* b2     = (const float*)d_in[5];
    const float* W3     = (const float*)d_in[6];
    const float* b3     = (const float*)d_in[7];
    const float* lin1_w = (const float*)d_in[8];
    const float* lin1_b = (const float*)d_in[9];
    const float* lin2_w = (const float*)d_in[10];
    const float* lin2_b = (const float*)d_in[11];
    float* out = (float*)d_out;

    int M = in_sizes[0] / F;
    int E = in_sizes[1] / 2;
    int NB = (M + 1023) / 1024;

    setup0_kernel<<<400, 256>>>((const unsigned int*)ei, lin2_w, lin2_b, M);
    cnt_hist_kernel<<<(E + 255) / 256, 256>>>(ei, E);
    chunksum_kernel<<<NB, 256>>>(M);
    scanblk_kernel<<<1, 128>>>(NB, M, E);
    chunkscan_kernel<<<NB, 256>>>(M);
    csr_fill_kernel<<<(E + 255) / 256, 256>>>(ei, E);

    int gb = (M + BM - 1) / BM;
    int wb = (int)(((long long)M * 32 + 255) / 256);

    // layer 1
    gemm_tc_kernel<<<gb, 256>>>(x, W1, b1, M, /*flags=*/2, /*asel=*/0);
    agg_kernel<<<wb, 256>>>(b1, M);
    // layer 2
    gemm_tc_kernel<<<gb, 256>>>(nullptr, W2, b2, M, /*flags=*/3, /*asel=*/1);
    agg_kernel<<<wb, 256>>>(b2, M);
    // layer 3
    gemm_tc_kernel<<<gb, 256>>>(nullptr, W3, b3, M, /*flags=*/3, /*asel=*/1);
    agg_kernel<<<wb, 256>>>(b3, M);
    // lin1: g_H = relu(relu(AGG) @ lin1_w + b)
    gemm_tc_kernel<<<gb, 256>>>(nullptr, lin1_w, lin1_b, M, /*flags=*/5, /*asel=*/1);
    // lin2 (padded weights): g_LOG = g_H @ W2p + b2p
    gemm_tc_kernel<<<gb, 256>>>(nullptr, nullptr, nullptr, M, /*flags=*/8, /*asel=*/2);
    // log_softmax
    lsm_kernel<<<wb, 256>>>(out, M);
}

// round 5
// speedup vs baseline: 4.1932x; 1.3358x over previous
#include <cuda_runtime.h>
#include <cuda_fp16.h>
#include <cstdint>
#include <cstddef>

// ---------------------------------------------------------------------------
// GCN: 3x GCNConv(128->128) + lin(128->128,relu) + lin(128->40) + log_softmax
// fp16 tensor-core GEMMs (fp32 accum), fp16 activations, CSR gather agg.
// ---------------------------------------------------------------------------

#define NMAX 100000
#define F    128
#define NCLS 40
#define EMAX 1600000

__device__ __half g_H[(size_t)NMAX * F];    // h * dinv[row]   (25.6 MB)
__device__ __half g_AGG[(size_t)NMAX * F];  // aggregate       (25.6 MB)
__device__ float  g_LOG[(size_t)NMAX * F];  // fp32 logits (cols < 40 used)
__device__ float  g_dinv[NMAX];
__device__ int    g_cnt[NMAX];
__device__ int    g_off[NMAX + 1];
__device__ int    g_cur[NMAX];
__device__ int    g_csr[EMAX];
__device__ __half g_Wh[5 * F * F];          // all weights, [n][k] fp16
__device__ float  g_b2p[F];
__device__ int    g_is64;

// ---------------------------------------------------------------------------
__device__ __forceinline__ float4 h4tof4(uint2 u) {
    __half2 a = *(__half2*)&u.x, b = *(__half2*)&u.y;
    float2 fa = __half22float2(a), fb = __half22float2(b);
    return make_float4(fa.x, fa.y, fb.x, fb.y);
}

// ---------------------------------------------------------------------------
// Setup: dtype detect + zero cnt + transpose/cvt all weights to fp16 [n][k]
// ---------------------------------------------------------------------------
__global__ void setup0_kernel(const unsigned int* __restrict__ w,
                              const float* __restrict__ W1,
                              const float* __restrict__ W2,
                              const float* __restrict__ W3,
                              const float* __restrict__ L1,
                              const float* __restrict__ L2,
                              const float* __restrict__ b2, int M) {
    if (blockIdx.x == 0) {
        __shared__ int found;
        if (threadIdx.x == 0) found = 0;
        __syncthreads();
        for (int i = threadIdx.x; i < 2048; i += blockDim.x)
            if (w[2 * i + 1] != 0u) atomicOr(&found, 1);
        __syncthreads();
        if (threadIdx.x == 0) g_is64 = found ? 0 : 1;
    }
    int stride = gridDim.x * blockDim.x;
    int tid0 = blockIdx.x * blockDim.x + threadIdx.x;
    for (int i = tid0; i < M; i += stride) g_cnt[i] = 0;
    for (int idx = tid0; idx < 5 * F * F; idx += stride) {
        int wi = idx >> 14;
        int r = idx & 16383;
        int n = r >> 7, k = r & 127;
        float v;
        switch (wi) {
            case 0: v = W1[k * F + n]; break;
            case 1: v = W2[k * F + n]; break;
            case 2: v = W3[k * F + n]; break;
            case 3: v = L1[k * F + n]; break;
            default: v = (n < NCLS) ? L2[k * NCLS + n] : 0.0f; break;
        }
        g_Wh[idx] = __float2half_rn(v);
    }
    for (int i = tid0; i < F; i += stride)
        g_b2p[i] = (i < NCLS) ? b2[i] : 0.0f;
}

__device__ __forceinline__ void load_edge(const void* ei, long long e, long long E,
                                          int& s, int& d) {
    if (g_is64) {
        const long long* p = (const long long*)ei;
        s = (int)p[e];
        d = (int)p[E + e];
    } else {
        const int* p = (const int*)ei;
        s = p[e];
        d = p[E + e];
    }
}

// ---------------------------------------------------------------------------
__global__ void cnt_hist_kernel(const void* __restrict__ ei, int E) {
    int e = blockIdx.x * blockDim.x + threadIdx.x;
    if (e >= E) return;
    int s, d;
    load_edge(ei, e, E, s, d);
    atomicAdd(&g_cnt[d], 1);
}

// Single-block fused scan: dinv + exclusive prefix of cnt -> off, cur
__global__ void __launch_bounds__(1024) scan_kernel(int M, int E) {
    __shared__ int warp_tot[32];
    __shared__ int warp_pref[32];
    int tid = threadIdx.x;
    int w = tid >> 5, lane = tid & 31;
    int R = (M + 31) / 32;           // region size per warp
    int base = w * R;

    int s = 0;
    for (int j = 0; j < R; j += 32) {
        int ir = j + lane;
        int i = base + ir;
        if (ir < R && i < M) {
            int c = g_cnt[i];
            s += c;
            g_dinv[i] = rsqrtf((float)c + 1.0f);
        }
    }
#pragma unroll
    for (int o = 16; o; o >>= 1) s += __shfl_xor_sync(0xffffffffu, s, o);
    if (lane == 0) warp_tot[w] = s;
    __syncthreads();
    if (w == 0) {
        int v = warp_tot[lane];
        int x = v;
#pragma unroll
        for (int o = 1; o < 32; o <<= 1) {
            int t = __shfl_up_sync(0xffffffffu, x, o);
            if (lane >= o) x += t;
        }
        warp_pref[lane] = x - v;
    }
    __syncthreads();
    int run = warp_pref[w];
    for (int j = 0; j < R; j += 32) {
        int ir = j + lane;
        int i = base + ir;
        int c = (ir < R && i < M) ? g_cnt[i] : 0;
        int x = c;
#pragma unroll
        for (int o = 1; o < 32; o <<= 1) {
            int t = __shfl_up_sync(0xffffffffu, x, o);
            if (lane >= o) x += t;
        }
        if (ir < R && i < M) {
            int p = run + x - c;
            g_off[i] = p;
            g_cur[i] = p;
        }
        run += __shfl_sync(0xffffffffu, x, 31);
    }
    if (tid == 0) g_off[M] = E;
}

__global__ void csr_fill_kernel(const void* __restrict__ ei, int E) {
    int e = blockIdx.x * blockDim.x + threadIdx.x;
    if (e >= E) return;
    int s, d;
    load_edge(ei, e, E, s, d);
    int p = atomicAdd(&g_cur[d], 1);
    g_csr[p] = s;
}

// ---------------------------------------------------------------------------
// fp16 tensor-core GEMM: C[M,128] = op(A)[M,128] @ Wt^T   (Wt is [n][k] fp16)
//  flags bit0: relu on A load
//  flags bit1: GCN out:   g_H = h * dinv[r]        (half)
//  flags bit2: lin1 out:  g_H = relu(h + b)        (half)
//  flags bit3: logit out: g_LOG = h + b (fp32, cols < NCLS)
//  asel: 0 = A param (fp32), 1 = g_AGG (half), 2 = g_H (half)
// ---------------------------------------------------------------------------
#define BM 128
#define BK 64

__device__ __forceinline__ void mma_f16(float* d, const uint32_t* a, const uint32_t* b) {
    asm volatile(
        "mma.sync.aligned.m16n8k16.row.col.f32.f16.f16.f32 "
        "{%0,%1,%2,%3}, {%4,%5,%6,%7}, {%8,%9}, {%0,%1,%2,%3};"
        : "+f"(d[0]), "+f"(d[1]), "+f"(d[2]), "+f"(d[3])
        : "r"(a[0]), "r"(a[1]), "r"(a[2]), "r"(a[3]), "r"(b[0]), "r"(b[1]));
}

__global__ void __launch_bounds__(256) gemm_tc_kernel(
    const float* __restrict__ A, const __half* __restrict__ Wt,
    const float* __restrict__ bias, int M, int flags, int asel)
{
    __shared__ __half As[BM][BK + 8];
    __shared__ __half Ws[F][BK + 8];

    const __half* Ah = (asel == 1) ? g_AGG : g_H;
    const float* bp = bias ? bias : g_b2p;
    const bool relu_in = flags & 1;
    const bool a_half = (asel != 0);

    const int tid = threadIdx.x;
    const int lane = tid & 31;
    const int wid = tid >> 5;
    const int wm = wid & 1;    // 2 warp-rows of 64
    const int wn = wid >> 1;   // 4 warp-cols of 32
    const int tg = lane >> 2;  // 0..7
    const int tm = lane & 3;   // 0..3
    const int row0 = blockIdx.x * BM;

    float acc[4][4][4];
#pragma unroll
    for (int mt = 0; mt < 4; mt++)
#pragma unroll
        for (int nt = 0; nt < 4; nt++)
#pragma unroll
            for (int j = 0; j < 4; j++) acc[mt][nt][j] = 0.0f;

    for (int k0 = 0; k0 < F; k0 += BK) {
        // A tile: 128 rows x 64 halves = 1024 slots of 8 halves, 4/thread
#pragma unroll
        for (int p = 0; p < 4; p++) {
            int s = p * 256 + tid;
            int r = s >> 3;
            int kq = (s & 7) * 8;
            int gr = row0 + r;
            uint2 h4a, h4b;
            if (gr < M) {
                size_t off = (size_t)gr * F + k0 + kq;
                if (a_half) {
                    uint4 u = *(const uint4*)(Ah + off);
                    h4a = make_uint2(u.x, u.y);
                    h4b = make_uint2(u.z, u.w);
                } else {
                    float4 v0 = *(const float4*)(A + off);
                    float4 v1 = *(const float4*)(A + off + 4);
                    __half2 a = __floats2half2_rn(v0.x, v0.y);
                    __half2 b = __floats2half2_rn(v0.z, v0.w);
                    __half2 c = __floats2half2_rn(v1.x, v1.y);
                    __half2 d = __floats2half2_rn(v1.z, v1.w);
                    h4a = make_uint2(*(uint32_t*)&a, *(uint32_t*)&b);
                    h4b = make_uint2(*(uint32_t*)&c, *(uint32_t*)&d);
                }
            } else {
                h4a = make_uint2(0u, 0u);
                h4b = make_uint2(0u, 0u);
            }
            if (relu_in) {
                __half2 z = __float2half2_rn(0.0f);
                *(__half2*)&h4a.x = __hmax2(*(__half2*)&h4a.x, z);
                *(__half2*)&h4a.y = __hmax2(*(__half2*)&h4a.y, z);
                *(__half2*)&h4b.x = __hmax2(*(__half2*)&h4b.x, z);
                *(__half2*)&h4b.y = __hmax2(*(__half2*)&h4b.y, z);
            }
            *(uint2*)&As[r][kq] = h4a;
            *(uint2*)&As[r][kq + 4] = h4b;
        }
        // W tile: Wt[n][k0..k0+63], 128 x 64 halves
#pragma unroll
        for (int p = 0; p < 4; p++) {
            int s = p * 256 + tid;
            int n = s >> 3;
            int kq = (s & 7) * 8;
            uint4 u = *(const uint4*)(Wt + (size_t)n * F + k0 + kq);
            *(uint2*)&Ws[n][kq] = make_uint2(u.x, u.y);
            *(uint2*)&Ws[n][kq + 4] = make_uint2(u.z, u.w);
        }
        __syncthreads();

#pragma unroll
        for (int kk = 0; kk < 4; kk++) {
            int kb = kk * 16;
            uint32_t af[4][4], bf[4][2];
#pragma unroll
            for (int mt = 0; mt < 4; mt++) {
                int rb = wm * 64 + mt * 16 + tg;
                af[mt][0] = *(uint32_t*)&As[rb][kb + 2 * tm];
                af[mt][1] = *(uint32_t*)&As[rb + 8][kb + 2 * tm];
                af[mt][2] = *(uint32_t*)&As[rb][kb + 2 * tm + 8];
                af[mt][3] = *(uint32_t*)&As[rb + 8][kb + 2 * tm + 8];
            }
#pragma unroll
            for (int nt = 0; nt < 4; nt++) {
                int nb = wn * 32 + nt * 8 + tg;
                bf[nt][0] = *(uint32_t*)&Ws[nb][kb + 2 * tm];
                bf[nt][1] = *(uint32_t*)&Ws[nb][kb + 2 * tm + 8];
            }
#pragma unroll
            for (int mt = 0; mt < 4; mt++)
#pragma unroll
                for (int nt = 0; nt < 4; nt++)
                    mma_f16(acc[mt][nt], af[mt], bf[nt]);
        }
        __syncthreads();
    }

    // Epilogue
#pragma unroll
    for (int mt = 0; mt < 4; mt++) {
        int r0 = row0 + wm * 64 + mt * 16 + tg;
        int r1 = r0 + 8;
        float dv0 = 0.f, dv1 = 0.f;
        if (flags & 2) {
            if (r0 < M) dv0 = g_dinv[r0];
            if (r1 < M) dv1 = g_dinv[r1];
        }
#pragma unroll
        for (int nt = 0; nt < 4; nt++) {
            int c = wn * 32 + nt * 8 + 2 * tm;
            float b0 = bp[c], b1 = bp[c + 1];
            float h00 = acc[mt][nt][0], h01 = acc[mt][nt][1];
            float h10 = acc[mt][nt][2], h11 = acc[mt][nt][3];
            if (flags & 2) {
                if (r0 < M)
                    *(__half2*)&g_H[(size_t)r0 * F + c] =
                        __floats2half2_rn(h00 * dv0, h01 * dv0);
                if (r1 < M)
                    *(__half2*)&g_H[(size_t)r1 * F + c] =
                        __floats2half2_rn(h10 * dv1, h11 * dv1);
            } else if (flags & 4) {
                if (r0 < M)
                    *(__half2*)&g_H[(size_t)r0 * F + c] =
                        __floats2half2_rn(fmaxf(h00 + b0, 0.f), fmaxf(h01 + b1, 0.f));
                if (r1 < M)
                    *(__half2*)&g_H[(size_t)r1 * F + c] =
                        __floats2half2_rn(fmaxf(h10 + b0, 0.f), fmaxf(h11 + b1, 0.f));
            } else {
                if (c < NCLS) {
                    if (r0 < M)
                        *(float2*)&g_LOG[(size_t)r0 * F + c] = make_float2(h00 + b0, h01 + b1);
                    if (r1 < M)
                        *(float2*)&g_LOG[(size_t)r1 * F + c] = make_float2(h10 + b0, h11 + b1);
                }
            }
        }
    }
}

// ---------------------------------------------------------------------------
// CSR aggregation, 16 lanes per node (uint4 = 8 halves per lane):
//   g_AGG[n] = dinv[n] * (sum_{s in N(n)} g_H[s] + g_H[n]) + bias
// ---------------------------------------------------------------------------
__global__ void agg_kernel(const float* __restrict__ bias, int M) {
    long long t = (long long)blockIdx.x * blockDim.x + threadIdx.x;
    long long n = t >> 4;
    if (n >= M) return;
    int lane = (int)(t & 15);
    const uint4* H = (const uint4*)g_H;  // 16 uint4 per row

    uint4 u = H[n * 16 + lane];
    float4 aclo = h4tof4(make_uint2(u.x, u.y));
    float4 achi = h4tof4(make_uint2(u.z, u.w));

    int e = g_off[n], e1 = g_off[n + 1];
    for (; e + 3 < e1; e += 4) {
        int s0 = __ldg(&g_csr[e]);
        int s1 = __ldg(&g_csr[e + 1]);
        int s2 = __ldg(&g_csr[e + 2]);
        int s3 = __ldg(&g_csr[e + 3]);
        uint4 u0 = H[(size_t)s0 * 16 + lane];
        uint4 u1 = H[(size_t)s1 * 16 + lane];
        uint4 u2 = H[(size_t)s2 * 16 + lane];
        uint4 u3 = H[(size_t)s3 * 16 + lane];
        float4 a0 = h4tof4(make_uint2(u0.x, u0.y)), b0 = h4tof4(make_uint2(u0.z, u0.w));
        float4 a1 = h4tof4(make_uint2(u1.x, u1.y)), b1 = h4tof4(make_uint2(u1.z, u1.w));
        float4 a2 = h4tof4(make_uint2(u2.x, u2.y)), b2 = h4tof4(make_uint2(u2.z, u2.w));
        float4 a3 = h4tof4(make_uint2(u3.x, u3.y)), b3 = h4tof4(make_uint2(u3.z, u3.w));
        aclo.x += (a0.x + a1.x) + (a2.x + a3.x);
        aclo.y += (a0.y + a1.y) + (a2.y + a3.y);
        aclo.z += (a0.z + a1.z) + (a2.z + a3.z);
        aclo.w += (a0.w + a1.w) + (a2.w + a3.w);
        achi.x += (b0.x + b1.x) + (b2.x + b3.x);
        achi.y += (b0.y + b1.y) + (b2.y + b3.y);
        achi.z += (b0.z + b1.z) + (b2.z + b3.z);
        achi.w += (b0.w + b1.w) + (b2.w + b3.w);
    }
    for (; e < e1; e++) {
        int s0 = __ldg(&g_csr[e]);
        uint4 u0 = H[(size_t)s0 * 16 + lane];
        float4 a0 = h4tof4(make_uint2(u0.x, u0.y)), b0 = h4tof4(make_uint2(u0.z, u0.w));
        aclo.x += a0.x; aclo.y += a0.y; aclo.z += a0.z; aclo.w += a0.w;
        achi.x += b0.x; achi.y += b0.y; achi.z += b0.z; achi.w += b0.w;
    }
    float dn = g_dinv[n];
    float4 blo = *(const float4*)(bias + lane * 8);
    float4 bhi = *(const float4*)(bias + lane * 8 + 4);
    __half2 o0 = __floats2half2_rn(fmaf(aclo.x, dn, blo.x), fmaf(aclo.y, dn, blo.y));
    __half2 o1 = __floats2half2_rn(fmaf(aclo.z, dn, blo.z), fmaf(aclo.w, dn, blo.w));
    __half2 o2 = __floats2half2_rn(fmaf(achi.x, dn, bhi.x), fmaf(achi.y, dn, bhi.y));
    __half2 o3 = __floats2half2_rn(fmaf(achi.z, dn, bhi.z), fmaf(achi.w, dn, bhi.w));
    uint4 out;
    out.x = *(uint32_t*)&o0; out.y = *(uint32_t*)&o1;
    out.z = *(uint32_t*)&o2; out.w = *(uint32_t*)&o3;
    ((uint4*)g_AGG)[n * 16 + lane] = out;
}

// ---------------------------------------------------------------------------
// log_softmax over 40 fp32 logits. One warp per node.
// ---------------------------------------------------------------------------
__global__ void lsm_kernel(float* __restrict__ out, int M) {
    long long gw = ((long long)blockIdx.x * blockDim.x + threadIdx.x) >> 5;
    if (gw >= M) return;
    int n = (int)gw;
    int lane = threadIdx.x & 31;
    float v0 = g_LOG[(size_t)n * F + lane];
    float v1 = (lane < 8) ? g_LOG[(size_t)n * F + 32 + lane] : -1e30f;
    float m = fmaxf(v0, v1);
#pragma unroll
    for (int o = 16; o; o >>= 1) m = fmaxf(m, __shfl_xor_sync(0xffffffffu, m, o));
    float s = expf(v0 - m) + ((lane < 8) ? expf(v1 - m) : 0.f);
#pragma unroll
    for (int o = 16; o; o >>= 1) s += __shfl_xor_sync(0xffffffffu, s, o);
    float lse = m + logf(s);
    out[(size_t)n * NCLS + lane] = v0 - lse;
    if (lane < 8) out[(size_t)n * NCLS + 32 + lane] = v1 - lse;
}

// ---------------------------------------------------------------------------
// Launch
// ---------------------------------------------------------------------------
extern "C" void kernel_launch(void* const* d_in, const int* in_sizes, int n_in,
                              void* d_out, int out_size) {
    const float* x      = (const float*)d_in[0];
    const void*  ei     = d_in[1];
    const float* W1     = (const float*)d_in[2];
    const float* b1     = (const float*)d_in[3];
    const float* W2     = (const float*)d_in[4];
    const float* b2     = (const float*)d_in[5];
    const float* W3     = (const float*)d_in[6];
    const float* b3     = (const float*)d_in[7];
    const float* lin1_w = (const float*)d_in[8];
    const float* lin1_b = (const float*)d_in[9];
    const float* lin2_w = (const float*)d_in[10];
    const float* lin2_b = (const float*)d_in[11];
    float* out = (float*)d_out;

    int M = in_sizes[0] / F;
    int E = in_sizes[1] / 2;

    __half* Wh1 = nullptr;  // device-symbol offsets resolved in-kernel via g_Wh
    (void)Wh1;

    setup0_kernel<<<400, 256>>>((const unsigned int*)ei, W1, W2, W3, lin1_w,
                                lin2_w, lin2_b, M);
    cnt_hist_kernel<<<(E + 255) / 256, 256>>>(ei, E);
    scan_kernel<<<1, 1024>>>(M, E);

    int gb = (M + BM - 1) / BM;
    int wb16 = (int)(((long long)M * 16 + 255) / 256);
    int wb32 = (int)(((long long)M * 32 + 255) / 256);

    __half* Wbase;
    cudaGetSymbolAddress((void**)&Wbase, g_Wh);

    // layer 1 GEMM (4th launch -> ncu capture target)
    gemm_tc_kernel<<<gb, 256>>>(x, Wbase + 0 * F * F, b1, M, /*flags=*/2, /*asel=*/0);
    csr_fill_kernel<<<(E + 255) / 256, 256>>>(ei, E);
    agg_kernel<<<wb16, 256>>>(b1, M);
    // layer 2
    gemm_tc_kernel<<<gb, 256>>>(nullptr, Wbase + 1 * F * F, b2, M, /*flags=*/3, /*asel=*/1);
    agg_kernel<<<wb16, 256>>>(b2, M);
    // layer 3
    gemm_tc_kernel<<<gb, 256>>>(nullptr, Wbase + 2 * F * F, b3, M, /*flags=*/3, /*asel=*/1);
    agg_kernel<<<wb16, 256>>>(b3, M);
    // lin1
    gemm_tc_kernel<<<gb, 256>>>(nullptr, Wbase + 3 * F * F, lin1_b, M, /*flags=*/5, /*asel=*/1);
    // lin2 (padded)
    gemm_tc_kernel<<<gb, 256>>>(nullptr, Wbase + 4 * F * F, nullptr, M, /*flags=*/8, /*asel=*/2);
    // log_softmax
    lsm_kernel<<<wb32, 256>>>(out, M);
}

// round 6
// speedup vs baseline: 4.3431x; 1.0358x over previous
#include <cuda_runtime.h>
#include <cuda_fp16.h>
#include <cstdint>
#include <cstddef>

// ---------------------------------------------------------------------------
// GCN: 3x GCNConv(128->128) + lin(128->128,relu) + lin(128->40) + log_softmax
// fp16 MMA GEMMs with ldmatrix + cp.async double buffering; CSR gather agg.
// ---------------------------------------------------------------------------

#define NMAX 100000
#define F    128
#define NCLS 40
#define EMAX 1600000

__device__ __half g_H[(size_t)NMAX * F];
__device__ __half g_AGG[(size_t)NMAX * F];
__device__ float  g_LOG[(size_t)NMAX * F];
__device__ float  g_dinv[NMAX];
__device__ int    g_cnt[NMAX];
__device__ int    g_off[NMAX + 1];
__device__ int    g_cur[NMAX];
__device__ int    g_csr[EMAX];
__device__ __half g_Wh[5 * F * F];
__device__ float  g_b2p[F];
__device__ int    g_is64;

__device__ __forceinline__ float4 h4tof4(uint2 u) {
    __half2 a = *(__half2*)&u.x, b = *(__half2*)&u.y;
    float2 fa = __half22float2(a), fb = __half22float2(b);
    return make_float4(fa.x, fa.y, fb.x, fb.y);
}

// ---------------------------------------------------------------------------
__global__ void setup0_kernel(const unsigned int* __restrict__ w,
                              const float* __restrict__ W1,
                              const float* __restrict__ W2,
                              const float* __restrict__ W3,
                              const float* __restrict__ L1,
                              const float* __restrict__ L2,
                              const float* __restrict__ b2, int M) {
    if (blockIdx.x == 0) {
        __shared__ int found;
        if (threadIdx.x == 0) found = 0;
        __syncthreads();
        for (int i = threadIdx.x; i < 2048; i += blockDim.x)
            if (w[2 * i + 1] != 0u) atomicOr(&found, 1);
        __syncthreads();
        if (threadIdx.x == 0) g_is64 = found ? 0 : 1;
    }
    int stride = gridDim.x * blockDim.x;
    int tid0 = blockIdx.x * blockDim.x + threadIdx.x;
    for (int i = tid0; i < M; i += stride) g_cnt[i] = 0;
    for (int idx = tid0; idx < 5 * F * F; idx += stride) {
        int wi = idx >> 14;
        int r = idx & 16383;
        int n = r >> 7, k = r & 127;
        float v;
        switch (wi) {
            case 0: v = W1[k * F + n]; break;
            case 1: v = W2[k * F + n]; break;
            case 2: v = W3[k * F + n]; break;
            case 3: v = L1[k * F + n]; break;
            default: v = (n < NCLS) ? L2[k * NCLS + n] : 0.0f; break;
        }
        g_Wh[idx] = __float2half_rn(v);
    }
    for (int i = tid0; i < F; i += stride)
        g_b2p[i] = (i < NCLS) ? b2[i] : 0.0f;
}

__device__ __forceinline__ void load_edge(const void* ei, long long e, long long E,
                                          int& s, int& d) {
    if (g_is64) {
        const long long* p = (const long long*)ei;
        s = (int)p[e];
        d = (int)p[E + e];
    } else {
        const int* p = (const int*)ei;
        s = p[e];
        d = p[E + e];
    }
}

__global__ void cnt_hist_kernel(const void* __restrict__ ei, int E) {
    int e = blockIdx.x * blockDim.x + threadIdx.x;
    if (e >= E) return;
    int s, d;
    load_edge(ei, e, E, s, d);
    atomicAdd(&g_cnt[d], 1);
}

__global__ void __launch_bounds__(1024) scan_kernel(int M, int E) {
    __shared__ int warp_tot[32];
    __shared__ int warp_pref[32];
    int tid = threadIdx.x;
    int w = tid >> 5, lane = tid & 31;
    int R = (M + 31) / 32;
    int base = w * R;

    int s = 0;
    for (int j = 0; j < R; j += 32) {
        int ir = j + lane;
        int i = base + ir;
        if (ir < R && i < M) {
            int c = g_cnt[i];
            s += c;
            g_dinv[i] = rsqrtf((float)c + 1.0f);
        }
    }
#pragma unroll
    for (int o = 16; o; o >>= 1) s += __shfl_xor_sync(0xffffffffu, s, o);
    if (lane == 0) warp_tot[w] = s;
    __syncthreads();
    if (w == 0) {
        int v = warp_tot[lane];
        int x = v;
#pragma unroll
        for (int o = 1; o < 32; o <<= 1) {
            int t = __shfl_up_sync(0xffffffffu, x, o);
            if (lane >= o) x += t;
        }
        warp_pref[lane] = x - v;
    }
    __syncthreads();
    int run = warp_pref[w];
    for (int j = 0; j < R; j += 32) {
        int ir = j + lane;
        int i = base + ir;
        int c = (ir < R && i < M) ? g_cnt[i] : 0;
        int x = c;
#pragma unroll
        for (int o = 1; o < 32; o <<= 1) {
            int t = __shfl_up_sync(0xffffffffu, x, o);
            if (lane >= o) x += t;
        }
        if (ir < R && i < M) {
            int p = run + x - c;
            g_off[i] = p;
            g_cur[i] = p;
        }
        run += __shfl_sync(0xffffffffu, x, 31);
    }
    if (tid == 0) g_off[M] = E;
}

__global__ void csr_fill_kernel(const void* __restrict__ ei, int E) {
    int e = blockIdx.x * blockDim.x + threadIdx.x;
    if (e >= E) return;
    int s, d;
    load_edge(ei, e, E, s, d);
    int p = atomicAdd(&g_cur[d], 1);
    g_csr[p] = s;
}

// ---------------------------------------------------------------------------
// fp16 MMA GEMM, ldmatrix + cp.async 2-stage pipeline.
// C[M,128] = op(A)[M,128] @ Wt^T   (Wt is [n][k] fp16)
//  flags bit1: GCN out:   g_H = h * dinv[r]
//  flags bit2: lin1 out:  g_H = relu(h + b)
//  flags bit3: logit out: g_LOG = h + b (fp32, cols < NCLS)
//  asel: 1 = g_AGG, 2 = g_H (AHALF=true); AHALF=false: A param fp32
// smem tile layout (per stage, 8KB): row r (64B = 4 chunks of 16B),
//   chunk c stored at r*64 + ((c ^ ((r>>1)&3))*16)  -> ldmatrix conflict-free
// ---------------------------------------------------------------------------
#define BM 128
#define BK 32

__device__ __forceinline__ void mma_f16(float* d, const uint32_t* a, const uint32_t* b) {
    asm volatile(
        "mma.sync.aligned.m16n8k16.row.col.f32.f16.f16.f32 "
        "{%0,%1,%2,%3}, {%4,%5,%6,%7}, {%8,%9}, {%0,%1,%2,%3};"
        : "+f"(d[0]), "+f"(d[1]), "+f"(d[2]), "+f"(d[3])
        : "r"(a[0]), "r"(a[1]), "r"(a[2]), "r"(a[3]), "r"(b[0]), "r"(b[1]));
}

__device__ __forceinline__ void ldmx4(uint32_t* r, uint32_t addr) {
    asm volatile("ldmatrix.sync.aligned.m8n8.x4.shared.b16 {%0,%1,%2,%3}, [%4];"
                 : "=r"(r[0]), "=r"(r[1]), "=r"(r[2]), "=r"(r[3]) : "r"(addr));
}

__device__ __forceinline__ void cp16(uint32_t dst, const void* src, int sz) {
    asm volatile("cp.async.cg.shared.global [%0], [%1], 16, %2;"
                 :: "r"(dst), "l"(src), "r"(sz));
}

template <bool AHALF>
__global__ void __launch_bounds__(256, 2) gemm_tc_kernel(
    const float* __restrict__ A, const __half* __restrict__ Wt,
    const float* __restrict__ bias, int M, int flags, int asel)
{
    __shared__ __align__(16) char sm[32768];  // A: 0/8192, B: 16384/24576
    uint32_t sbase;
    asm("{ .reg .u64 t; cvta.to.shared.u64 t, %1; cvt.u32.u64 %0, t; }"
        : "=r"(sbase) : "l"(sm));

    const __half* Ah = (asel == 1) ? g_AGG : g_H;
    const float* bp = bias ? bias : g_b2p;

    const int tid = threadIdx.x;
    const int lane = tid & 31;
    const int wid = tid >> 5;
    const int wm = wid & 1;
    const int wn = wid >> 1;
    const int tg = lane >> 2;
    const int tm = lane & 3;
    const int row0 = blockIdx.x * BM;

    // Loader indices: 2 chunks per thread per tile (512 chunks of 16B)
    const int lr = tid >> 2;          // rows 0..63 (+64 on second pass)
    const int lc = tid & 3;           // chunk 0..3

    auto load_stage = [&](int kt, int stage) {
        int k0 = kt * BK;
#pragma unroll
        for (int p = 0; p < 2; p++) {
            int r = lr + p * 64;
            uint32_t doff = sbase + stage * 8192 +
                            (uint32_t)(r * 64 + ((lc ^ ((r >> 1) & 3)) << 4));
            if (AHALF) {
                int gr = row0 + r;
                int ok = (gr < M) ? 16 : 0;
                int grc = (gr < M) ? gr : (M - 1);
                cp16(doff, Ah + (size_t)grc * F + k0 + lc * 8, ok);
            } else {
                int gr = row0 + r;
                float4 v0, v1;
                if (gr < M) {
                    size_t o = (size_t)gr * F + k0 + lc * 8;
                    v0 = *(const float4*)(A + o);
                    v1 = *(const float4*)(A + o + 4);
                } else {
                    v0 = v1 = make_float4(0.f, 0.f, 0.f, 0.f);
                }
                __half2 a = __floats2half2_rn(v0.x, v0.y);
                __half2 b = __floats2half2_rn(v0.z, v0.w);
                __half2 c = __floats2half2_rn(v1.x, v1.y);
                __half2 d = __floats2half2_rn(v1.z, v1.w);
                uint4 u;
                u.x = *(uint32_t*)&a; u.y = *(uint32_t*)&b;
                u.z = *(uint32_t*)&c; u.w = *(uint32_t*)&d;
                asm volatile("st.shared.v4.b32 [%0], {%1,%2,%3,%4};"
                             :: "r"(doff), "r"(u.x), "r"(u.y), "r"(u.z), "r"(u.w));
            }
            // B (weights, always fp16)
            uint32_t boff = sbase + 16384 + stage * 8192 +
                            (uint32_t)(r * 64 + ((lc ^ ((r >> 1) & 3)) << 4));
            cp16(boff, Wt + (size_t)r * F + k0 + lc * 8, 16);
        }
        asm volatile("cp.async.commit_group;" ::: "memory");
    };

    float acc[4][4][4];
#pragma unroll
    for (int mt = 0; mt < 4; mt++)
#pragma unroll
        for (int nt = 0; nt < 4; nt++)
#pragma unroll
            for (int j = 0; j < 4; j++) acc[mt][nt][j] = 0.0f;

    load_stage(0, 0);

#pragma unroll
    for (int kt = 0; kt < 4; kt++) {
        int cur = kt & 1;
        if (kt < 3) load_stage(kt + 1, cur ^ 1);
        if (kt < 3) asm volatile("cp.async.wait_group 1;" ::: "memory");
        else        asm volatile("cp.async.wait_group 0;" ::: "memory");
        __syncthreads();

        uint32_t sa = sbase + cur * 8192;
        uint32_t sb = sbase + 16384 + cur * 8192;

#pragma unroll
        for (int kb = 0; kb < 2; kb++) {
            uint32_t af[4][4], bf[2][4];
#pragma unroll
            for (int mt = 0; mt < 4; mt++) {
                int row = wm * 64 + mt * 16 + (lane & 15);
                int cc = kb * 2 + (lane >> 4);
                ldmx4(af[mt], sa + row * 64 + ((cc ^ ((row >> 1) & 3)) << 4));
            }
#pragma unroll
            for (int q = 0; q < 2; q++) {
                int n = wn * 32 + q * 16 + ((lane >> 4) << 3) + (lane & 7);
                int cc = kb * 2 + ((lane >> 3) & 1);
                ldmx4(bf[q], sb + n * 64 + ((cc ^ ((n >> 1) & 3)) << 4));
            }
#pragma unroll
            for (int mt = 0; mt < 4; mt++)
#pragma unroll
                for (int nt = 0; nt < 4; nt++)
                    mma_f16(acc[mt][nt], af[mt], &bf[nt >> 1][2 * (nt & 1)]);
        }
        __syncthreads();
    }

    // Epilogue
#pragma unroll
    for (int mt = 0; mt < 4; mt++) {
        int r0 = row0 + wm * 64 + mt * 16 + tg;
        int r1 = r0 + 8;
        float dv0 = 0.f, dv1 = 0.f;
        if (flags & 2) {
            if (r0 < M) dv0 = g_dinv[r0];
            if (r1 < M) dv1 = g_dinv[r1];
        }
#pragma unroll
        for (int nt = 0; nt < 4; nt++) {
            int c = wn * 32 + nt * 8 + 2 * tm;
            float b0 = bp[c], b1 = bp[c + 1];
            float h00 = acc[mt][nt][0], h01 = acc[mt][nt][1];
            float h10 = acc[mt][nt][2], h11 = acc[mt][nt][3];
            if (flags & 2) {
                if (r0 < M)
                    *(__half2*)&g_H[(size_t)r0 * F + c] =
                        __floats2half2_rn(h00 * dv0, h01 * dv0);
                if (r1 < M)
                    *(__half2*)&g_H[(size_t)r1 * F + c] =
                        __floats2half2_rn(h10 * dv1, h11 * dv1);
            } else if (flags & 4) {
                if (r0 < M)
                    *(__half2*)&g_H[(size_t)r0 * F + c] =
                        __floats2half2_rn(fmaxf(h00 + b0, 0.f), fmaxf(h01 + b1, 0.f));
                if (r1 < M)
                    *(__half2*)&g_H[(size_t)r1 * F + c] =
                        __floats2half2_rn(fmaxf(h10 + b0, 0.f), fmaxf(h11 + b1, 0.f));
            } else {
                if (c < NCLS) {
                    if (r0 < M)
                        *(float2*)&g_LOG[(size_t)r0 * F + c] = make_float2(h00 + b0, h01 + b1);
                    if (r1 < M)
                        *(float2*)&g_LOG[(size_t)r1 * F + c] = make_float2(h10 + b0, h11 + b1);
                }
            }
        }
    }
}

// ---------------------------------------------------------------------------
// CSR aggregation, 16 lanes per node:
//   g_AGG[n] = relu( dinv[n] * (sum g_H[src] + g_H[n]) + bias )
// (All AGG consumers apply relu, so fold it here.)
// ---------------------------------------------------------------------------
__global__ void agg_kernel(const float* __restrict__ bias, int M) {
    long long t = (long long)blockIdx.x * blockDim.x + threadIdx.x;
    long long n = t >> 4;
    if (n >= M) return;
    int lane = (int)(t & 15);
    const uint4* H = (const uint4*)g_H;

    uint4 u = H[n * 16 + lane];
    float4 aclo = h4tof4(make_uint2(u.x, u.y));
    float4 achi = h4tof4(make_uint2(u.z, u.w));

    int e = g_off[n], e1 = g_off[n + 1];
    for (; e + 3 < e1; e += 4) {
        int s0 = __ldg(&g_csr[e]);
        int s1 = __ldg(&g_csr[e + 1]);
        int s2 = __ldg(&g_csr[e + 2]);
        int s3 = __ldg(&g_csr[e + 3]);
        uint4 u0 = H[(size_t)s0 * 16 + lane];
        uint4 u1 = H[(size_t)s1 * 16 + lane];
        uint4 u2 = H[(size_t)s2 * 16 + lane];
        uint4 u3 = H[(size_t)s3 * 16 + lane];
        float4 a0 = h4tof4(make_uint2(u0.x, u0.y)), b0 = h4tof4(make_uint2(u0.z, u0.w));
        float4 a1 = h4tof4(make_uint2(u1.x, u1.y)), b1 = h4tof4(make_uint2(u1.z, u1.w));
        float4 a2 = h4tof4(make_uint2(u2.x, u2.y)), b2 = h4tof4(make_uint2(u2.z, u2.w));
        float4 a3 = h4tof4(make_uint2(u3.x, u3.y)), b3 = h4tof4(make_uint2(u3.z, u3.w));
        aclo.x += (a0.x + a1.x) + (a2.x + a3.x);
        aclo.y += (a0.y + a1.y) + (a2.y + a3.y);
        aclo.z += (a0.z + a1.z) + (a2.z + a3.z);
        aclo.w += (a0.w + a1.w) + (a2.w + a3.w);
        achi.x += (b0.x + b1.x) + (b2.x + b3.x);
        achi.y += (b0.y + b1.y) + (b2.y + b3.y);
        achi.z += (b0.z + b1.z) + (b2.z + b3.z);
        achi.w += (b0.w + b1.w) + (b2.w + b3.w);
    }
    for (; e < e1; e++) {
        int s0 = __ldg(&g_csr[e]);
        uint4 u0 = H[(size_t)s0 * 16 + lane];
        float4 a0 = h4tof4(make_uint2(u0.x, u0.y)), b0 = h4tof4(make_uint2(u0.z, u0.w));
        aclo.x += a0.x; aclo.y += a0.y; aclo.z += a0.z; aclo.w += a0.w;
        achi.x += b0.x; achi.y += b0.y; achi.z += b0.z; achi.w += b0.w;
    }
    float dn = g_dinv[n];
    float4 blo = *(const float4*)(bias + lane * 8);
    float4 bhi = *(const float4*)(bias + lane * 8 + 4);
    __half2 o0 = __floats2half2_rn(fmaxf(fmaf(aclo.x, dn, blo.x), 0.f),
                                   fmaxf(fmaf(aclo.y, dn, blo.y), 0.f));
    __half2 o1 = __floats2half2_rn(fmaxf(fmaf(aclo.z, dn, blo.z), 0.f),
                                   fmaxf(fmaf(aclo.w, dn, blo.w), 0.f));
    __half2 o2 = __floats2half2_rn(fmaxf(fmaf(achi.x, dn, bhi.x), 0.f),
                                   fmaxf(fmaf(achi.y, dn, bhi.y), 0.f));
    __half2 o3 = __floats2half2_rn(fmaxf(fmaf(achi.z, dn, bhi.z), 0.f),
                                   fmaxf(fmaf(achi.w, dn, bhi.w), 0.f));
    uint4 outv;
    outv.x = *(uint32_t*)&o0; outv.y = *(uint32_t*)&o1;
    outv.z = *(uint32_t*)&o2; outv.w = *(uint32_t*)&o3;
    ((uint4*)g_AGG)[n * 16 + lane] = outv;
}

// ---------------------------------------------------------------------------
__global__ void lsm_kernel(float* __restrict__ out, int M) {
    long long gw = ((long long)blockIdx.x * blockDim.x + threadIdx.x) >> 5;
    if (gw >= M) return;
    int n = (int)gw;
    int lane = threadIdx.x & 31;
    float v0 = g_LOG[(size_t)n * F + lane];
    float v1 = (lane < 8) ? g_LOG[(size_t)n * F + 32 + lane] : -1e30f;
    float m = fmaxf(v0, v1);
#pragma unroll
    for (int o = 16; o; o >>= 1) m = fmaxf(m, __shfl_xor_sync(0xffffffffu, m, o));
    float s = expf(v0 - m) + ((lane < 8) ? expf(v1 - m) : 0.f);
#pragma unroll
    for (int o = 16; o; o >>= 1) s += __shfl_xor_sync(0xffffffffu, s, o);
    float lse = m + logf(s);
    out[(size_t)n * NCLS + lane] = v0 - lse;
    if (lane < 8) out[(size_t)n * NCLS + 32 + lane] = v1 - lse;
}

// ---------------------------------------------------------------------------
extern "C" void kernel_launch(void* const* d_in, const int* in_sizes, int n_in,
                              void* d_out, int out_size) {
    const float* x      = (const float*)d_in[0];
    const void*  ei     = d_in[1];
    const float* W1     = (const float*)d_in[2];
    const float* b1     = (const float*)d_in[3];
    const float* W2     = (const float*)d_in[4];
    const float* b2     = (const float*)d_in[5];
    const float* W3     = (const float*)d_in[6];
    const float* b3     = (const float*)d_in[7];
    const float* lin1_w = (const float*)d_in[8];
    const float* lin1_b = (const float*)d_in[9];
    const float* lin2_w = (const float*)d_in[10];
    const float* lin2_b = (const float*)d_in[11];
    float* out = (float*)d_out;

    int M = in_sizes[0] / F;
    int E = in_sizes[1] / 2;

    setup0_kernel<<<400, 256>>>((const unsigned int*)ei, W1, W2, W3, lin1_w,
                                lin2_w, lin2_b, M);
    cnt_hist_kernel<<<(E + 255) / 256, 256>>>(ei, E);
    scan_kernel<<<1, 1024>>>(M, E);

    int gb = (M + BM - 1) / BM;
    int wb16 = (int)(((long long)M * 16 + 255) / 256);
    int wb32 = (int)(((long long)M * 32 + 255) / 256);

    __half* Wbase;
    cudaGetSymbolAddress((void**)&Wbase, g_Wh);

    // layer 1 GEMM (4th launch -> ncu capture target)
    gemm_tc_kernel<false><<<gb, 256>>>(x, Wbase + 0 * F * F, b1, M, 2, 0);
    csr_fill_kernel<<<(E + 255) / 256, 256>>>(ei, E);
    agg_kernel<<<wb16, 256>>>(b1, M);
    // layer 2
    gemm_tc_kernel<true><<<gb, 256>>>(nullptr, Wbase + 1 * F * F, b2, M, 2, 1);
    agg_kernel<<<wb16, 256>>>(b2, M);
    // layer 3
    gemm_tc_kernel<true><<<gb, 256>>>(nullptr, Wbase + 2 * F * F, b3, M, 2, 1);
    agg_kernel<<<wb16, 256>>>(b3, M);
    // lin1
    gemm_tc_kernel<true><<<gb, 256>>>(nullptr, Wbase + 3 * F * F, lin1_b, M, 4, 1);
    // lin2 (padded weights)
    gemm_tc_kernel<true><<<gb, 256>>>(nullptr, Wbase + 4 * F * F, nullptr, M, 8, 2);
    // log_softmax
    lsm_kernel<<<wb32, 256>>>(out, M);
}